// round 3
// baseline (speedup 1.0000x reference)
#include <cuda_runtime.h>
#include <math.h>

#define BB 2
#define C  19
#define H  128
#define W  128
#define CH 320
#define CG 32          // coarse grid 32x32
#define HW (H*W)

// Reference (XLA GPU exp, MUFU-based) flushes subnormal f32 outputs to zero.
// Emulate: any sim below FLT_MIN (2^-126) becomes exactly 0.
#define F32_FLUSH_THRESH 1.1754943508222875e-38

// ---------------- scratch (__device__ globals; no allocation) ----------------
__device__ float  g_prob[BB * C * HW];          // softmax(logits) (B,C,H,W)
__device__ float  g_F[BB * CG * CG * CH];       // x_ema transposed: (B,cell,ch)
__device__ double g_S[BB * CG * CG * 10];       // sim table: 9 offsets + [9]=oob (FTZ-emulated)
__device__ double g_acc[2];                     // sum loc_pos, sum loc_neg (masked)
__device__ int    g_nmask;                      // mask count

// ---------------- 0: zero accumulators ----------------
__global__ void init_k() {
    g_acc[0] = 0.0; g_acc[1] = 0.0; g_nmask = 0;
}

// ---------------- 1: softmax over C=19 ----------------
__global__ void softmax_k(const float* __restrict__ logits) {
    int bi = blockIdx.x;             // b*H + i
    int b  = bi / H, i = bi % H;
    int j  = threadIdx.x;
    const float* base = logits + (size_t)b * C * HW + i * W + j;
    float v[C];
    float m = -INFINITY;
#pragma unroll
    for (int c = 0; c < C; c++) { v[c] = base[c * HW]; m = fmaxf(m, v[c]); }
    float s = 0.f;
#pragma unroll
    for (int c = 0; c < C; c++) { v[c] = expf(v[c] - m); s += v[c]; }
    float inv = 1.f / s;
    float* out = g_prob + (size_t)b * C * HW + i * W + j;
#pragma unroll
    for (int c = 0; c < C; c++) out[c * HW] = v[c] * inv;
}

// ---------------- 2: transpose x_ema (B,CH,32,32) -> (B,cell,CH) ----------------
__global__ void transpose_k(const float* __restrict__ x) {
    __shared__ float tile[32][33];
    int b   = blockIdx.z;
    int ct  = blockIdx.x;   // cell tile
    int cht = blockIdx.y;   // channel tile
    int cell = ct * 32 + threadIdx.x;
    int ch   = cht * 32 + threadIdx.y;
    tile[threadIdx.y][threadIdx.x] = x[((size_t)b * CH + ch) * (CG * CG) + cell];
    __syncthreads();
    int cell2 = ct * 32 + threadIdx.y;
    int ch2   = cht * 32 + threadIdx.x;
    g_F[((size_t)b * CG * CG + cell2) * CH + ch2] = tile[threadIdx.x][threadIdx.y];
}

// ---------------- 3: coarse-cell similarity table ----------------
__global__ void simtab_k() {
    int b    = blockIdx.x >> 10;
    int cell = blockIdx.x & 1023;
    int ci = cell >> 5, cj = cell & 31;
    int c = threadIdx.x;

    float fc = g_F[((size_t)b * CG * CG + cell) * CH + c];
    float acc[10];
#pragma unroll
    for (int k = 0; k < 9; k++) {
        int dci = k / 3 - 1, dcj = k % 3 - 1;
        int ni = ci + dci, nj = cj + dcj;
        if (ni >= 0 && ni < CG && nj >= 0 && nj < CG) {
            float fn = g_F[((size_t)b * CG * CG + ni * CG + nj) * CH + c];
            float d = fn - fc;
            acc[k] = d * d;
        } else {
            acc[k] = 0.f;   // unused by pixel kernel
        }
    }
    acc[9] = fc * fc;       // ||center||^2 for zero-padded (OOB) neighbors

    __shared__ float sm[10][11];
    int lane = threadIdx.x & 31, wid = threadIdx.x >> 5;
#pragma unroll
    for (int s = 0; s < 10; s++) {
        float v = acc[s];
#pragma unroll
        for (int off = 16; off; off >>= 1) v += __shfl_down_sync(0xffffffffu, v, off);
        if (lane == 0) sm[wid][s] = v;
    }
    __syncthreads();
    if (threadIdx.x < 10) {
        float s = 0.f;
#pragma unroll
        for (int w = 0; w < 10; w++) s += sm[w][threadIdx.x];
        double t = exp(-(double)s * 0.25);               // deterministic double exp
        if (t < F32_FLUSH_THRESH) t = 0.0;               // emulate reference's FTZ exp
        g_S[((size_t)b * CG * CG + cell) * 10 + threadIdx.x] = t;
    }
}

// ---------------- 4: per-pixel loss ----------------
__global__ void pixel_k(const float* __restrict__ x_ema) {
    int bi = blockIdx.x;
    int b  = bi / H, i = bi % H;
    int j  = threadIdx.x;

    const float* P = g_prob + (size_t)b * C * HW;
    float p[C];
    float sum_p = 0.f;
    {
        const float* pc = P + i * W + j;
#pragma unroll
        for (int c = 0; c < C; c++) { p[c] = pc[c * HW]; sum_p += p[c]; }
    }

    int ci = i >> 2, cj = j >> 2;
    const double* Sc = g_S + ((size_t)b * CG * CG + ci * CG + cj) * 10;
    double sim_oob = Sc[9];

    double sim[9];
    float  cp[9], cn[9];
#pragma unroll
    for (int k = 0; k < 9; k++) {
        int a  = k / 3, bb2 = k % 3;
        int ni = i + (a - 1) * 2;
        int nj = j + (bb2 - 1) * 2;
        if (ni < 0 || ni >= H || nj < 0 || nj >= W) {
            sim[k] = sim_oob; cp[k] = 0.f; cn[k] = 0.f;
        } else {
            const float* Q = P + ni * W + nj;
            float cpos = 0.f, sq = 0.f;
#pragma unroll
            for (int c = 0; c < C; c++) { float q = Q[c * HW]; cpos += p[c] * q; sq += q; }
            cp[k] = cpos;
            cn[k] = sum_p * sq - cpos;
            int dci = (ni >> 2) - ci, dcj = (nj >> 2) - cj;
            sim[k] = Sc[(dci + 1) * 3 + (dcj + 1)];
        }
    }

    // top-(K+1)=5 largest sims (stable: lowest index wins ties, like jax top_k)
    float lpos = 0.f;
    {
        bool used[9];
#pragma unroll
        for (int k = 0; k < 9; k++) used[k] = false;
#pragma unroll
        for (int t = 0; t < 5; t++) {
            double bv = -1.0; float bcp = 0.f; int sel = -1;
#pragma unroll
            for (int k = 0; k < 9; k++) {
                if (!used[k] && sim[k] > bv) { bv = sim[k]; bcp = cp[k]; sel = k; }
            }
#pragma unroll
            for (int k = 0; k < 9; k++) used[k] = used[k] || (k == sel);
            lpos += (float)bv * (-bcp);
        }
    }
    // 4 smallest sims (stable lowest-index ties, like top_k(-sim))
    float lneg = 0.f;
    {
        bool used[9];
#pragma unroll
        for (int k = 0; k < 9; k++) used[k] = false;
#pragma unroll
        for (int t = 0; t < 4; t++) {
            double bv = 2.0; float bcn = 0.f; int sel = -1;
#pragma unroll
            for (int k = 0; k < 9; k++) {
                if (!used[k] && sim[k] < bv) { bv = sim[k]; bcn = cn[k]; sel = k; }
            }
#pragma unroll
            for (int k = 0; k < 9; k++) used[k] = used[k] || (k == sel);
            lneg += (1.f - (float)bv) * (-bcn);
        }
    }

    // mask = feats[:,0,:,:] > 0  ==  x_ema[b,0,ci,cj] > 0
    bool msk = x_ema[(size_t)b * CH * CG * CG + ci * CG + cj] > 0.f;
    float mlp = msk ? lpos : 0.f;
    float mln = msk ? lneg : 0.f;
    int   mc  = msk ? 1 : 0;

    // block reduce (128 threads = 4 warps)
    __shared__ float s0[4], s1[4];
    __shared__ int   s2[4];
#pragma unroll
    for (int off = 16; off; off >>= 1) {
        mlp += __shfl_down_sync(0xffffffffu, mlp, off);
        mln += __shfl_down_sync(0xffffffffu, mln, off);
        mc  += __shfl_down_sync(0xffffffffu, mc,  off);
    }
    int lane = threadIdx.x & 31, wid = threadIdx.x >> 5;
    if (lane == 0) { s0[wid] = mlp; s1[wid] = mln; s2[wid] = mc; }
    __syncthreads();
    if (threadIdx.x == 0) {
        double a0 = (double)s0[0] + s0[1] + s0[2] + s0[3];
        double a1 = (double)s1[0] + s1[1] + s1[2] + s1[3];
        int    a2 = s2[0] + s2[1] + s2[2] + s2[3];
        atomicAdd(&g_acc[0], a0);
        atomicAdd(&g_acc[1], a1);
        atomicAdd(&g_nmask, a2);
    }
}

// ---------------- 5: finalize ----------------
__global__ void final_k(float* __restrict__ out) {
    float nm = (float)g_nmask;
    out[0] = (float)g_acc[0] / (nm * 5.0f);   // W_POS = 1
    out[1] = (float)g_acc[1] / (nm * 4.0f);   // W_NEG = 1
}

// ---------------- launch ----------------
extern "C" void kernel_launch(void* const* d_in, const int* in_sizes, int n_in,
                              void* d_out, int out_size) {
    const float* logits = (const float*)d_in[0];  // (2,19,128,128)
    const float* x_ema  = (const float*)d_in[1];  // (2,320,32,32)
    // d_in[2] = img_trg, unused by the reference.
    float* out = (float*)d_out;

    init_k<<<1, 1>>>();
    softmax_k<<<BB * H, W>>>(logits);
    transpose_k<<<dim3(32, 10, BB), dim3(32, 32)>>>(x_ema);
    simtab_k<<<BB * CG * CG, CH>>>();
    pixel_k<<<BB * H, W>>>(x_ema);
    final_k<<<1, 1>>>(out);
}

// round 4
// speedup vs baseline: 1.5078x; 1.5078x over previous
#include <cuda_runtime.h>
#include <math.h>

#define BB 2
#define C  19
#define H  128
#define W  128
#define CH 320
#define CG 32          // coarse grid 32x32
#define HW (H*W)
#define NPIX_BLK (BB*H)            // 256 pixel/softmax blocks
#define NTRANS_BLK (BB*(CG*CG/32)*(CH/32))   // 2*32*10 = 640 transpose tiles

// Reference exp (XLA GPU, MUFU-based) flushes subnormal f32 outputs to zero.
#define F32_FLUSH_THRESH 1.1754943508222875e-38

// ---------------- scratch (__device__ globals; no allocation) ----------------
__device__ float    g_prob[BB * C * HW];       // softmax(logits) (B,C,H,W)
__device__ float    g_F[BB * CG * CG * CH];    // x_ema transposed: (B,cell,ch)
__device__ float    g_Sd[BB * CG * CG * 5];    // per cell: sims for E,SW,S,SE dirs + oob sim
__device__ double   g_acc[2];                  // masked sums: loc_pos, loc_neg
__device__ int      g_nmask;                   // mask count
__device__ unsigned g_done = 0;                // last-block ticket (self-resetting)

// ---------------- 1: fused init + softmax + transpose ----------------
__global__ void pre_k(const float* __restrict__ logits, const float* __restrict__ x) {
    int blk = blockIdx.x;
    int t   = threadIdx.x;
    if (blk == 0 && t == 0) { g_acc[0] = 0.0; g_acc[1] = 0.0; g_nmask = 0; }

    if (blk < NPIX_BLK) {
        // ---- softmax over C=19 for one image row ----
        int b = blk / H, i = blk % H;
        const float* base = logits + (size_t)b * C * HW + i * W + t;
        float v[C];
        float m = -INFINITY;
#pragma unroll
        for (int c = 0; c < C; c++) { v[c] = base[c * HW]; m = fmaxf(m, v[c]); }
        float s = 0.f;
#pragma unroll
        for (int c = 0; c < C; c++) { v[c] = expf(v[c] - m); s += v[c]; }
        float inv = 1.f / s;
        float* out = g_prob + (size_t)b * C * HW + i * W + t;
#pragma unroll
        for (int c = 0; c < C; c++) out[c * HW] = v[c] * inv;
    } else {
        // ---- transpose x_ema (B,CH,32,32) -> (B,cell,CH), 32x32 tile, 128 thr ----
        __shared__ float tile[32][33];
        int tb  = blk - NPIX_BLK;        // 0..639
        int bz  = tb / (NTRANS_BLK / BB);
        int tt  = tb % (NTRANS_BLK / BB);
        int ct  = tt & 31;               // cell tile 0..31
        int cht = tt >> 5;               // channel tile 0..9
        int tx = t & 31, ty = t >> 5;    // 4 rows per iteration
#pragma unroll
        for (int r = 0; r < 32; r += 4)
            tile[ty + r][tx] = x[((size_t)bz * CH + cht * 32 + ty + r) * (CG * CG) + ct * 32 + tx];
        __syncthreads();
#pragma unroll
        for (int r = 0; r < 32; r += 4)
            g_F[((size_t)bz * CG * CG + ct * 32 + ty + r) * CH + cht * 32 + tx] = tile[tx][ty + r];
    }
}

// ---------------- 2: directed coarse-cell sim table ----------------
// block = (b, cell), 128 threads; threads [0,80) each own one float4 of channels.
// Directed dists: e0=(0,+1) E, e1=(+1,-1) SW, e2=(+1,0) S, e3=(+1,+1) SE, e4=||f||^2.
__global__ void simtab_k() {
    int blk  = blockIdx.x;
    int b    = blk >> 10;
    int cell = blk & 1023;
    int ci = cell >> 5, cj = cell & 31;
    int t = threadIdx.x;

    const float4* F4 = (const float4*)g_F;
    const float4* base = F4 + (size_t)b * CG * CG * (CH / 4);

    float acc[5] = {0.f, 0.f, 0.f, 0.f, 0.f};
    if (t < CH / 4) {
        float4 c = base[cell * (CH / 4) + t];
        acc[4] = c.x * c.x + c.y * c.y + c.z * c.z + c.w * c.w;
        if (cj + 1 < CG) {
            float4 n = base[(cell + 1) * (CH / 4) + t];
            float dx = n.x - c.x, dy = n.y - c.y, dz = n.z - c.z, dw = n.w - c.w;
            acc[0] = dx * dx + dy * dy + dz * dz + dw * dw;
        }
        if (ci + 1 < CG) {
            int s = cell + CG;
            if (cj - 1 >= 0) {
                float4 n = base[(s - 1) * (CH / 4) + t];
                float dx = n.x - c.x, dy = n.y - c.y, dz = n.z - c.z, dw = n.w - c.w;
                acc[1] = dx * dx + dy * dy + dz * dz + dw * dw;
            }
            {
                float4 n = base[s * (CH / 4) + t];
                float dx = n.x - c.x, dy = n.y - c.y, dz = n.z - c.z, dw = n.w - c.w;
                acc[2] = dx * dx + dy * dy + dz * dz + dw * dw;
            }
            if (cj + 1 < CG) {
                float4 n = base[(s + 1) * (CH / 4) + t];
                float dx = n.x - c.x, dy = n.y - c.y, dz = n.z - c.z, dw = n.w - c.w;
                acc[3] = dx * dx + dy * dy + dz * dz + dw * dw;
            }
        }
    }

    __shared__ float sm[4][5];
    int lane = t & 31, w = t >> 5;
#pragma unroll
    for (int e = 0; e < 5; e++) {
        float v = acc[e];
#pragma unroll
        for (int off = 16; off; off >>= 1) v += __shfl_down_sync(0xffffffffu, v, off);
        if (lane == 0) sm[w][e] = v;
    }
    __syncthreads();
    if (t == 0) {
        float* out = g_Sd + (size_t)(b * CG * CG + cell) * 5;
#pragma unroll
        for (int e = 0; e < 5; e++) {
            float s = sm[0][e] + sm[1][e] + sm[2][e] + sm[3][e];
            double tt = exp(-(double)s * 0.25);          // FTZ-immune double exp
            if (tt < F32_FLUSH_THRESH) tt = 0.0;         // emulate reference FTZ
            out[e] = (float)tt;
        }
    }
}

// ---------------- 3: per-pixel loss (+ fused finalize) ----------------
__global__ void pixel_k(const float* __restrict__ x_ema, float* __restrict__ out) {
    int bi = blockIdx.x;
    int b  = bi / H, i = bi % H;
    int j  = threadIdx.x;

    const float* P = g_prob + (size_t)b * C * HW;
    float p[C];
    float sum_p = 0.f;
    {
        const float* pc = P + i * W + j;
#pragma unroll
        for (int c = 0; c < C; c++) { p[c] = pc[c * HW]; sum_p += p[c]; }
    }

    int ci = i >> 2, cj = j >> 2;
    const float* Sb = g_Sd + (size_t)b * CG * CG * 5;
    float sim_oob = Sb[(ci * CG + cj) * 5 + 4];

    float sim[9], cp[9], cn[9];
#pragma unroll
    for (int k = 0; k < 9; k++) {
        int a  = k / 3, b2 = k % 3;
        int ni = i + (a - 1) * 2;
        int nj = j + (b2 - 1) * 2;
        if (ni < 0 || ni >= H || nj < 0 || nj >= W) {
            sim[k] = sim_oob; cp[k] = 0.f; cn[k] = 0.f;
        } else {
            const float* Q = P + ni * W + nj;
            float cpos = 0.f, sq = 0.f;
#pragma unroll
            for (int c = 0; c < C; c++) { float q = Q[c * HW]; cpos += p[c] * q; sq += q; }
            cp[k] = cpos;
            cn[k] = sum_p * sq - cpos;
            int dci = (ni >> 2) - ci;
            int dcj = (nj >> 2) - cj;
            float sv;
            if ((dci | dcj) == 0)      sv = 1.0f;
            else if (dci < 0)          sv = Sb[((ci - 1) * CG + cj + dcj) * 5 + (2 - dcj)];
            else if (dci > 0)          sv = Sb[(ci * CG + cj) * 5 + (2 + dcj)];
            else if (dcj > 0)          sv = Sb[(ci * CG + cj) * 5 + 0];
            else                       sv = Sb[(ci * CG + cj - 1) * 5 + 0];
            sim[k] = sv;
        }
    }

    // top-5 largest sims (stable: lowest index wins ties, like jax top_k)
    float lpos = 0.f;
    {
        bool used[9];
#pragma unroll
        for (int k = 0; k < 9; k++) used[k] = false;
#pragma unroll
        for (int t = 0; t < 5; t++) {
            float bv = -1.f, bcp = 0.f; int sel = -1;
#pragma unroll
            for (int k = 0; k < 9; k++)
                if (!used[k] && sim[k] > bv) { bv = sim[k]; bcp = cp[k]; sel = k; }
#pragma unroll
            for (int k = 0; k < 9; k++) used[k] = used[k] || (k == sel);
            lpos += bv * (-bcp);
        }
    }
    // bottom-4 sims (stable lowest-index ties, like top_k(-sim))
    float lneg = 0.f;
    {
        bool used[9];
#pragma unroll
        for (int k = 0; k < 9; k++) used[k] = false;
#pragma unroll
        for (int t = 0; t < 4; t++) {
            float bv = 2.f, bcn = 0.f; int sel = -1;
#pragma unroll
            for (int k = 0; k < 9; k++)
                if (!used[k] && sim[k] < bv) { bv = sim[k]; bcn = cn[k]; sel = k; }
#pragma unroll
            for (int k = 0; k < 9; k++) used[k] = used[k] || (k == sel);
            lneg += (1.f - bv) * (-bcn);
        }
    }

    // mask = feats[:,0,:,:] > 0  ==  x_ema[b,0,ci,cj] > 0
    bool msk = x_ema[(size_t)b * CH * CG * CG + ci * CG + cj] > 0.f;
    float mlp = msk ? lpos : 0.f;
    float mln = msk ? lneg : 0.f;
    int   mc  = msk ? 1 : 0;

    // block reduce (4 warps)
    __shared__ float s0[4], s1[4];
    __shared__ int   s2[4];
#pragma unroll
    for (int off = 16; off; off >>= 1) {
        mlp += __shfl_down_sync(0xffffffffu, mlp, off);
        mln += __shfl_down_sync(0xffffffffu, mln, off);
        mc  += __shfl_down_sync(0xffffffffu, mc,  off);
    }
    int lane = threadIdx.x & 31, wid = threadIdx.x >> 5;
    if (lane == 0) { s0[wid] = mlp; s1[wid] = mln; s2[wid] = mc; }
    __syncthreads();
    if (threadIdx.x == 0) {
        double a0 = (double)s0[0] + s0[1] + s0[2] + s0[3];
        double a1 = (double)s1[0] + s1[1] + s1[2] + s1[3];
        int    a2 = s2[0] + s2[1] + s2[2] + s2[3];
        atomicAdd(&g_acc[0], a0);
        atomicAdd(&g_acc[1], a1);
        atomicAdd(&g_nmask, a2);
        __threadfence();
        unsigned old = atomicInc(&g_done, NPIX_BLK - 1);   // wraps to 0 -> replay-safe
        if (old == NPIX_BLK - 1) {
            double p0 = atomicAdd(&g_acc[0], 0.0);
            double p1 = atomicAdd(&g_acc[1], 0.0);
            int    nm = atomicAdd(&g_nmask, 0);
            out[0] = (float)p0 / ((float)nm * 5.0f);   // W_POS = 1
            out[1] = (float)p1 / ((float)nm * 4.0f);   // W_NEG = 1
        }
    }
}

// ---------------- launch ----------------
extern "C" void kernel_launch(void* const* d_in, const int* in_sizes, int n_in,
                              void* d_out, int out_size) {
    const float* logits = (const float*)d_in[0];  // (2,19,128,128)
    const float* x_ema  = (const float*)d_in[1];  // (2,320,32,32)
    // d_in[2] = img_trg, unused by the reference.
    float* out = (float*)d_out;

    pre_k<<<NPIX_BLK + NTRANS_BLK, 128>>>(logits, x_ema);
    simtab_k<<<BB * CG * CG, 128>>>();
    pixel_k<<<NPIX_BLK, 128>>>(x_ema, out);
}